// round 15
// baseline (speedup 1.0000x reference)
#include <cuda_runtime.h>
#include <cuda_bf16.h>
#include <cstdint>
#include <math.h>

#define EDIM 512
#define HEADS 8
#define DHD 64
#define KNN 32
#define NMAX 2048
#define CLAMPV 10000.0f
#define WSZ (EDIM * EDIM)

// ---- scratch (no allocations allowed) ----
__device__ float g_cent[NMAX * 3];
__device__ __nv_bfloat16 g_peh[NMAX * EDIM];
__device__ __nv_bfloat16 g_pel[NMAX * EDIM];
__device__ float g_q[NMAX * EDIM];    // QKV q; later WO partial 0
__device__ float g_k[NMAX * EDIM];    // QKV k; later WO partial 1
__device__ float g_v[NMAX * EDIM];
__device__ __nv_bfloat16 g_ch[NMAX * EDIM];
__device__ __nv_bfloat16 g_cl[NMAX * EDIM];
__device__ __nv_bfloat16 g_wh[4 * WSZ];   // q,k,v,o hi
__device__ __nv_bfloat16 g_wl[4 * WSZ];   // q,k,v,o lo
__device__ int   g_topk[NMAX * KNN];

// ---- streams/events for parallel graph branches ----
static cudaStream_t s_side = 0;
static cudaEvent_t ev_fork = 0, ev_join = 0, ev_fork2 = 0, ev_join2 = 0;
struct StreamInit {
    StreamInit() {
        cudaStreamCreateWithFlags(&s_side, cudaStreamNonBlocking);
        cudaEventCreateWithFlags(&ev_fork,  cudaEventDisableTiming);
        cudaEventCreateWithFlags(&ev_join,  cudaEventDisableTiming);
        cudaEventCreateWithFlags(&ev_fork2, cudaEventDisableTiming);
        cudaEventCreateWithFlags(&ev_join2, cudaEventDisableTiming);
    }
};
static StreamInit g_stream_init;

// ---- helpers ----
__device__ __forceinline__ void split_bf16(float v, __nv_bfloat16& h, __nv_bfloat16& l) {
    h = __float2bfloat16_rn(v);
    l = __float2bfloat16_rn(v - __bfloat162float(h));
}
__device__ __forceinline__ uint32_t smem_u32(const void* p) {
    uint32_t a;
    asm("{ .reg .u64 t; cvta.to.shared.u64 t, %1; cvt.u32.u64 %0, t; }" : "=r"(a) : "l"(p));
    return a;
}
__device__ __forceinline__ void cp16(uint32_t dst, const void* src, bool pred) {
    uint32_t sz = pred ? 16u : 0u;
    asm volatile("cp.async.cg.shared.global [%0], [%1], 16, %2;"
                 :: "r"(dst), "l"(src), "r"(sz) : "memory");
}
#define CP_COMMIT() asm volatile("cp.async.commit_group;" ::: "memory")
#define CP_WAIT(n)  asm volatile("cp.async.wait_group %0;" :: "n"(n) : "memory")

__device__ __forceinline__ void mma_bf16(float* d, const uint32_t* a, const uint32_t* b) {
    asm volatile(
        "mma.sync.aligned.m16n8k16.row.col.f32.bf16.bf16.f32 "
        "{%0,%1,%2,%3}, {%4,%5,%6,%7}, {%8,%9}, {%0,%1,%2,%3};\n"
        : "+f"(d[0]), "+f"(d[1]), "+f"(d[2]), "+f"(d[3])
        : "r"(a[0]), "r"(a[1]), "r"(a[2]), "r"(a[3]), "r"(b[0]), "r"(b[1]));
}

// ===================================================================
// 1) centroids
// ===================================================================
__global__ void centroid_kernel(const float* __restrict__ coords9,
                                float* __restrict__ cent, int N) {
    int i = blockIdx.x * blockDim.x + threadIdx.x;
    if (i >= N) return;
    const float inv3 = 1.0f / 3.0f;
#pragma unroll
    for (int c = 0; c < 3; c++) {
        float s = coords9[i * 9 + c] + coords9[i * 9 + 3 + c] + coords9[i * 9 + 6 + c];
        cent[i * 3 + c] = s * inv3;
    }
}

// ===================================================================
// 2) weight convert: fp32 -> bf16 hi/lo for wq,wk,wv,wo
// ===================================================================
__global__ void convert_w_kernel(const float* __restrict__ wq, const float* __restrict__ wk,
                                 const float* __restrict__ wv, const float* __restrict__ wo) {
    int w = blockIdx.y;
    const float* src = (w == 0) ? wq : (w == 1) ? wk : (w == 2) ? wv : wo;
    __nv_bfloat16* hd = g_wh + (size_t)w * WSZ;
    __nv_bfloat16* ld = g_wl + (size_t)w * WSZ;
    int idx = (blockIdx.x * 256 + threadIdx.x) * 4;
    float4 v = *(const float4*)(src + idx);
    __nv_bfloat16 h0, h1, h2, h3, l0, l1, l2, l3;
    split_bf16(v.x, h0, l0); split_bf16(v.y, h1, l1);
    split_bf16(v.z, h2, l2); split_bf16(v.w, h3, l3);
    *(__nv_bfloat162*)(hd + idx)     = __nv_bfloat162(h0, h1);
    *(__nv_bfloat162*)(hd + idx + 2) = __nv_bfloat162(h2, h3);
    *(__nv_bfloat162*)(ld + idx)     = __nv_bfloat162(l0, l1);
    *(__nv_bfloat162*)(ld + idx + 2) = __nv_bfloat162(l2, l3);
}

// ===================================================================
// 3) pos encoder + assembly, writes pe directly as bf16 hi/lo
// ===================================================================
__global__ void posenc_kernel(const float* __restrict__ x,
                              const float* __restrict__ prompt,
                              const float* __restrict__ cent,
                              const float* __restrict__ w1,
                              const float* __restrict__ b1,
                              const float* __restrict__ lng,
                              const float* __restrict__ lnb,
                              __nv_bfloat16* __restrict__ peh,
                              __nv_bfloat16* __restrict__ pel, int N) {
    int i = blockIdx.x;
    int t = threadIdx.x;   // 0..127
    __shared__ float red[128];

    float cx = cent[i * 3 + 0], cy = cent[i * 3 + 1], cz = cent[i * 3 + 2];
    float h = cx * w1[t * 3 + 0] + cy * w1[t * 3 + 1] + cz * w1[t * 3 + 2] + b1[t];
    float gel = 0.5f * h * (1.0f + erff(h * 0.70710678118654752f));

    red[t] = gel;
    __syncthreads();
    for (int s = 64; s > 0; s >>= 1) { if (t < s) red[t] += red[t + s]; __syncthreads(); }
    float mu = red[0] * (1.0f / 128.0f);
    __syncthreads();
    float d = gel - mu;
    red[t] = d * d;
    __syncthreads();
    for (int s = 64; s > 0; s >>= 1) { if (t < s) red[t] += red[t + s]; __syncthreads(); }
    float var = red[0] * (1.0f / 128.0f);
    float y = d * rsqrtf(var + 1e-5f) * lng[t] + lnb[t];

    __nv_bfloat16 hh, ll;
    split_bf16(y, hh, ll);
    peh[(size_t)i * EDIM + 384 + t] = hh;
    pel[(size_t)i * EDIM + 384 + t] = ll;
    for (int c = t; c < 384; c += 128) {
        float v = x[(size_t)i * EDIM + c] + prompt[c];
        split_bf16(v, hh, ll);
        peh[(size_t)i * EDIM + c] = hh;
        pel[(size_t)i * EDIM + c] = ll;
    }
}

// ===================================================================
// 4) per-row k-NN top-32 via radix select on float bits (set semantics;
//    tie-break lower index in boundary bin = jax.lax.top_k).
// ===================================================================
#define TKBINS 2048
__global__ void __launch_bounds__(256)
topk_kernel(const float* __restrict__ cent, int* __restrict__ topk, int N) {
    __shared__ uint32_t keys[NMAX];
    __shared__ int      hist[TKBINS];
    __shared__ uint32_t bufk[NMAX];
    __shared__ uint16_t bufi[NMAX];
    __shared__ int      s_below, s_buf, s_binB, s_cbelow;

    int i = blockIdx.x;
    int t = threadIdx.x;

    for (int b = t; b < TKBINS; b += 256) hist[b] = 0;
    if (t == 0) { s_below = 0; s_buf = 0; }
    __syncthreads();

    float xi = cent[3 * i], yi = cent[3 * i + 1], zi = cent[3 * i + 2];
    for (int j = t; j < N; j += 256) {
        float dx = xi - cent[3 * j], dy = yi - cent[3 * j + 1], dz = zi - cent[3 * j + 2];
        float d = sqrtf(dx * dx + dy * dy + dz * dz);
        uint32_t key = __float_as_uint(d);
        keys[j] = key;
        atomicAdd(&hist[key >> 21], 1);
    }
    __syncthreads();

    if (t < 32) {
        int s = 0;
#pragma unroll
        for (int b = 0; b < 64; b++) s += hist[t * 64 + b];
        int excl = s;
#pragma unroll
        for (int off = 1; off < 32; off <<= 1) {
            int n = __shfl_up_sync(0xffffffffu, excl, off);
            if ((t & 31) >= off) excl += n;
        }
        excl -= s;
        if (excl < KNN && KNN <= excl + s) {
            int base = excl;
            for (int b = 0; b < 64; b++) {
                int h = hist[t * 64 + b];
                if (base < KNN && KNN <= base + h) {
                    s_binB = t * 64 + b;
                    s_cbelow = base;
                    break;
                }
                base += h;
            }
        }
    }
    __syncthreads();
    int binB = s_binB;
    int cbelow = s_cbelow;

    for (int j = t; j < N; j += 256) {
        uint32_t key = keys[j];
        int b = key >> 21;
        if (b < binB) {
            int slot = atomicAdd(&s_below, 1);
            topk[i * KNN + slot] = j;
        } else if (b == binB) {
            int s = atomicAdd(&s_buf, 1);
            bufk[s] = key;
            bufi[s] = (uint16_t)j;
        }
    }
    __syncthreads();

    int nb = s_buf;
    int need = KNN - cbelow;
    for (int e = t; e < nb; e += 256) {
        uint32_t ke = bufk[e];
        int ie = bufi[e];
        int rank = 0;
        for (int f = 0; f < nb; f++) {
            uint32_t kf = bufk[f];
            if (kf < ke || (kf == ke && (int)bufi[f] < ie)) rank++;
        }
        if (rank < need) topk[i * KNN + cbelow + rank] = ie;
    }
}

// ===================================================================
// 5) bf16 split GEMM with cp.async double buffering; runtime K-range.
//    (R13-proven scalar-LDS fragment path.)
// ===================================================================
#define KC 32
#define LSTRIDE 40
#define MATSZ (128 * LSTRIDE)
#define GSMEM (2 * 4 * MATSZ * 2)

__global__ void __launch_bounds__(256, 2)
gemm_bf16_split(const __nv_bfloat16* __restrict__ Ahi, const __nv_bfloat16* __restrict__ Alo,
                const __nv_bfloat16* __restrict__ Bh0, const __nv_bfloat16* __restrict__ Bl0,
                const __nv_bfloat16* __restrict__ Bh1, const __nv_bfloat16* __restrict__ Bl1,
                const __nv_bfloat16* __restrict__ Bh2, const __nv_bfloat16* __restrict__ Bl2,
                const float* __restrict__ bias0, const float* __restrict__ bias1,
                const float* __restrict__ bias2,
                float* __restrict__ C0, float* __restrict__ C1, float* __restrict__ C2,
                int M, int kstart, int knch, int addbias) {
    extern __shared__ __nv_bfloat16 sm[];
    uint32_t smb = smem_u32(sm);

    int tid  = threadIdx.x;
    int wid  = tid >> 5;
    int lane = tid & 31;
    int wm   = wid >> 2;
    int wn   = wid & 3;

    int sel = blockIdx.x >> 2;
    int bn  = (blockIdx.x & 3) * 128;
    int bm  = blockIdx.y * 128;

    const __nv_bfloat16* Bh = (sel == 0) ? Bh0 : (sel == 1) ? Bh1 : Bh2;
    const __nv_bfloat16* Bl = (sel == 0) ? Bl0 : (sel == 1) ? Bl1 : Bl2;
    const float* bias = (sel == 0) ? bias0 : (sel == 1) ? bias1 : bias2;
    float*       C    = (sel == 0) ? C0 : (sel == 1) ? C1 : C2;

    float acc[4][4][4];
#pragma unroll
    for (int a = 0; a < 4; a++)
#pragma unroll
        for (int b = 0; b < 4; b++)
#pragma unroll
            for (int c = 0; c < 4; c++) acc[a][b][c] = 0.0f;

    auto load_stage = [&](int s, int ch) {
        int kt = ch * KC;
        uint32_t sb = smb + (uint32_t)s * 4 * MATSZ * 2;
        for (int i = tid; i < 512; i += 256) {
            int row = i >> 2;
            int c   = (i & 3) * 8;
            uint32_t off = (uint32_t)(row * LSTRIDE + c) * 2;
            int am = bm + row;
            bool av = am < M;
            int amc = av ? am : 0;
            cp16(sb + off,             Ahi + (size_t)amc * EDIM + kt + c, av);
            cp16(sb + MATSZ * 2 + off, Alo + (size_t)amc * EDIM + kt + c, av);
            cp16(sb + MATSZ * 4 + off, Bh + (size_t)(bn + row) * EDIM + kt + c, true);
            cp16(sb + MATSZ * 6 + off, Bl + (size_t)(bn + row) * EDIM + kt + c, true);
        }
    };

    load_stage(0, kstart);
    CP_COMMIT();

    for (int cc = 0; cc < knch; cc++) {
        int s = cc & 1;
        if (cc + 1 < knch) {
            load_stage(s ^ 1, kstart + cc + 1);
            CP_COMMIT();
            CP_WAIT(1);
        } else {
            CP_WAIT(0);
        }
        __syncthreads();

        const __nv_bfloat16* base = sm + (size_t)s * 4 * MATSZ;
#pragma unroll
        for (int term = 0; term < 3; term++) {
            const __nv_bfloat16* As = base + (term == 2 ? MATSZ : 0);
            const __nv_bfloat16* Bs = base + 2 * MATSZ + (term == 1 ? MATSZ : 0);
#pragma unroll
            for (int ks = 0; ks < 2; ks++) {
                int k0 = ks * 16 + 2 * (lane & 3);
                uint32_t afr[4][4];
                uint32_t bfr[4][2];
#pragma unroll
                for (int mt = 0; mt < 4; mt++) {
                    int r = wm * 64 + mt * 16 + (lane >> 2);
                    const __nv_bfloat16* p = As + r * LSTRIDE + k0;
                    afr[mt][0] = *(const uint32_t*)p;
                    afr[mt][1] = *(const uint32_t*)(p + 8 * LSTRIDE);
                    afr[mt][2] = *(const uint32_t*)(p + 8);
                    afr[mt][3] = *(const uint32_t*)(p + 8 * LSTRIDE + 8);
                }
#pragma unroll
                for (int nt = 0; nt < 4; nt++) {
                    int n = wn * 32 + nt * 8 + (lane >> 2);
                    const __nv_bfloat16* p = Bs + n * LSTRIDE + k0;
                    bfr[nt][0] = *(const uint32_t*)p;
                    bfr[nt][1] = *(const uint32_t*)(p + 8);
                }
#pragma unroll
                for (int mt = 0; mt < 4; mt++)
#pragma unroll
                    for (int nt = 0; nt < 4; nt++)
                        mma_bf16(acc[mt][nt], afr[mt], bfr[nt]);
            }
        }
        __syncthreads();
    }

#pragma unroll
    for (int mt = 0; mt < 4; mt++) {
#pragma unroll
        for (int nt = 0; nt < 4; nt++) {
            int row0 = bm + wm * 64 + mt * 16 + (lane >> 2);
            int col  = bn + wn * 32 + nt * 8 + 2 * (lane & 3);
            float b0 = addbias ? bias[col] : 0.0f;
            float b1 = addbias ? bias[col + 1] : 0.0f;
#pragma unroll
            for (int half = 0; half < 2; half++) {
                int r = row0 + half * 8;
                if (r < M) {
                    float v0 = acc[mt][nt][half * 2 + 0] + b0;
                    float v1 = acc[mt][nt][half * 2 + 1] + b1;
                    *(float2*)(C + (size_t)r * EDIM + col) = make_float2(v0, v1);
                }
            }
        }
    }
}

// ===================================================================
// 6) sparse gather attention v2: lane = neighbor for the score phase.
//    Block = 1 query, 256 threads = 8 head-warps.
// ===================================================================
__global__ void __launch_bounds__(256)
attn_kernel(const float* __restrict__ q,
            const float* __restrict__ k,
            const float* __restrict__ v,
            const int* __restrict__ topk,
            __nv_bfloat16* __restrict__ ctxh,
            __nv_bfloat16* __restrict__ ctxl, int N) {
    int i = blockIdx.x;
    int lane = threadIdx.x & 31;
    int h = threadIdx.x >> 5;
    __shared__ int   idx_s[KNN];
    __shared__ float q_s[EDIM];

    if (threadIdx.x < KNN) idx_s[threadIdx.x] = topk[i * KNN + threadIdx.x];
    // stage query row in smem (256 threads x 2 floats)
    ((float2*)q_s)[threadIdx.x] = ((const float2*)(q + (size_t)i * EDIM))[threadIdx.x];
    __syncthreads();

    // ---- score phase: lane j computes q[h] . k[m_j][h] ----
    int m = idx_s[lane];
    const float* krow = k + (size_t)m * EDIM + h * DHD;
    const float* qh = q_s + h * DHD;
    float s = 0.0f;
#pragma unroll
    for (int d = 0; d < DHD; d += 4) {
        float4 k4 = *(const float4*)(krow + d);
        s += qh[d] * k4.x + qh[d + 1] * k4.y + qh[d + 2] * k4.z + qh[d + 3] * k4.w;
    }
    s *= 0.125f;   // 1/sqrt(64)

    // softmax across 32 lanes
    float mx = s;
#pragma unroll
    for (int off = 16; off; off >>= 1) mx = fmaxf(mx, __shfl_xor_sync(0xffffffffu, mx, off));
    float e = expf(s - mx);
    float sum = e;
#pragma unroll
    for (int off = 16; off; off >>= 1) sum += __shfl_xor_sync(0xffffffffu, sum, off);
    float p = e / sum;

    // ---- V phase: lane = 2 dims, broadcast p_j ----
    float2 acc = make_float2(0.f, 0.f);
#pragma unroll
    for (int j = 0; j < KNN; j++) {
        float pj = __shfl_sync(0xffffffffu, p, j);
        int mj = idx_s[j];
        float2 v2 = *(const float2*)(v + (size_t)mj * EDIM + h * DHD + 2 * lane);
        acc.x += pj * v2.x;
        acc.y += pj * v2.y;
    }
    __nv_bfloat16 h0, l0, h1, l1;
    split_bf16(acc.x, h0, l0);
    split_bf16(acc.y, h1, l1);
    size_t o = (size_t)i * EDIM + h * DHD + 2 * lane;
    *(__nv_bfloat162*)(ctxh + o) = __nv_bfloat162(h0, h1);
    *(__nv_bfloat162*)(ctxl + o) = __nv_bfloat162(l0, l1);
}

// ===================================================================
// 7) combine split-K partials + bias, sanitize, clamp -> out
// ===================================================================
__global__ void combine_kernel(const float* __restrict__ p0, const float* __restrict__ p1,
                               const float* __restrict__ bias, float* __restrict__ out,
                               int total4) {
    int i = blockIdx.x * 256 + threadIdx.x;
    if (i >= total4) return;
    int idx = i * 4;
    float4 a = *(const float4*)(p0 + idx);
    float4 b = *(const float4*)(p1 + idx);
    float4 bs = *(const float4*)(bias + (idx & (EDIM - 1)));
    float v0 = a.x + b.x + bs.x;
    float v1 = a.y + b.y + bs.y;
    float v2 = a.z + b.z + bs.z;
    float v3 = a.w + b.w + bs.w;
    if (isnan(v0)) v0 = 0.0f;
    if (isnan(v1)) v1 = 0.0f;
    if (isnan(v2)) v2 = 0.0f;
    if (isnan(v3)) v3 = 0.0f;
    v0 = fminf(fmaxf(v0, -CLAMPV), CLAMPV);
    v1 = fminf(fmaxf(v1, -CLAMPV), CLAMPV);
    v2 = fminf(fmaxf(v2, -CLAMPV), CLAMPV);
    v3 = fminf(fmaxf(v3, -CLAMPV), CLAMPV);
    *(float4*)(out + idx) = make_float4(v0, v1, v2, v3);
}

// ===================================================================
extern "C" void kernel_launch(void* const* d_in, const int* in_sizes, int n_in,
                              void* d_out, int out_size) {
    const float* x       = (const float*)d_in[0];
    const float* coords9 = (const float*)d_in[1];
    const float* prompt  = (const float*)d_in[2];
    const float* pw1     = (const float*)d_in[3];
    const float* pb1     = (const float*)d_in[4];
    const float* plng    = (const float*)d_in[5];
    const float* plnb    = (const float*)d_in[6];
    const float* wq      = (const float*)d_in[7];
    const float* wk      = (const float*)d_in[8];
    const float* wv      = (const float*)d_in[9];
    const float* bq      = (const float*)d_in[10];
    const float* bk      = (const float*)d_in[11];
    const float* bv      = (const float*)d_in[12];
    const float* wo      = (const float*)d_in[13];
    const float* bo      = (const float*)d_in[14];

    int N = in_sizes[1] / 9;

    float *cent, *qp, *kp, *vp;
    __nv_bfloat16 *peh, *pel, *ch, *cl, *wh, *wl;
    int* tk;
    cudaGetSymbolAddress((void**)&cent, g_cent);
    cudaGetSymbolAddress((void**)&peh,  g_peh);
    cudaGetSymbolAddress((void**)&pel,  g_pel);
    cudaGetSymbolAddress((void**)&qp,   g_q);
    cudaGetSymbolAddress((void**)&kp,   g_k);
    cudaGetSymbolAddress((void**)&vp,   g_v);
    cudaGetSymbolAddress((void**)&ch,   g_ch);
    cudaGetSymbolAddress((void**)&cl,   g_cl);
    cudaGetSymbolAddress((void**)&wh,   g_wh);
    cudaGetSymbolAddress((void**)&wl,   g_wl);
    cudaGetSymbolAddress((void**)&tk,   g_topk);

    cudaFuncSetAttribute(gemm_bf16_split, cudaFuncAttributeMaxDynamicSharedMemorySize, GSMEM);

    // --- main stream: centroid, then fork topk to side stream ---
    centroid_kernel<<<(N + 255) / 256, 256>>>(coords9, cent, N);
    cudaEventRecord(ev_fork, 0);
    cudaStreamWaitEvent(s_side, ev_fork, 0);
    topk_kernel<<<N, 256, 0, s_side>>>(cent, tk, N);
    cudaEventRecord(ev_join, s_side);

    // --- main stream GEMM branch ---
    convert_w_kernel<<<dim3(256, 4), 256>>>(wq, wk, wv, wo);
    posenc_kernel<<<N, 128>>>(x, prompt, cent, pw1, pb1, plng, plnb, peh, pel, N);

    int mt = (N + 127) / 128;
    gemm_bf16_split<<<dim3(12, mt), 256, GSMEM>>>(
        peh, pel,
        wh + 0 * WSZ, wl + 0 * WSZ, wh + 1 * WSZ, wl + 1 * WSZ, wh + 2 * WSZ, wl + 2 * WSZ,
        bq, bk, bv, qp, kp, vp, N, 0, 16, 1);

    // --- join topk, run attention ---
    cudaStreamWaitEvent(0, ev_join, 0);
    attn_kernel<<<N, 256>>>(qp, kp, vp, tk, ch, cl, N);

    // --- WO split-K across the two streams; q/k buffers reused as partials ---
    cudaEventRecord(ev_fork2, 0);
    cudaStreamWaitEvent(s_side, ev_fork2, 0);
    gemm_bf16_split<<<dim3(4, mt), 256, GSMEM, s_side>>>(
        ch, cl,
        wh + 3 * WSZ, wl + 3 * WSZ, wh + 3 * WSZ, wl + 3 * WSZ, wh + 3 * WSZ, wl + 3 * WSZ,
        bo, bo, bo, kp, kp, kp, N, 8, 8, 0);
    cudaEventRecord(ev_join2, s_side);
    gemm_bf16_split<<<dim3(4, mt), 256, GSMEM>>>(
        ch, cl,
        wh + 3 * WSZ, wl + 3 * WSZ, wh + 3 * WSZ, wl + 3 * WSZ, wh + 3 * WSZ, wl + 3 * WSZ,
        bo, bo, bo, qp, qp, qp, N, 0, 8, 0);
    cudaStreamWaitEvent(0, ev_join2, 0);

    int total4 = N * EDIM / 4;
    combine_kernel<<<(total4 + 255) / 256, 256>>>(qp, kp, bo, (float*)d_out, total4);
}

// round 16
// speedup vs baseline: 1.9066x; 1.9066x over previous
#include <cuda_runtime.h>
#include <cuda_bf16.h>
#include <cstdint>
#include <math.h>

#define EDIM 512
#define HEADS 8
#define DHD 64
#define KNN 32
#define NMAX 2048
#define CLAMPV 10000.0f
#define WSZ (EDIM * EDIM)

// ---- scratch (no allocations allowed) ----
__device__ float g_cent[NMAX * 3];
__device__ __nv_bfloat16 g_peh[NMAX * EDIM];
__device__ __nv_bfloat16 g_pel[NMAX * EDIM];
__device__ float g_q[NMAX * EDIM];    // QKV q; later WO partial 0
__device__ float g_k[NMAX * EDIM];    // QKV k; later WO partial 1
__device__ float g_v[NMAX * EDIM];
__device__ __nv_bfloat16 g_ch[NMAX * EDIM];
__device__ __nv_bfloat16 g_cl[NMAX * EDIM];
__device__ __nv_bfloat16 g_wh[4 * WSZ];   // q,k,v,o hi
__device__ __nv_bfloat16 g_wl[4 * WSZ];   // q,k,v,o lo
__device__ int   g_topk[NMAX * KNN];

// ---- streams/events for parallel graph branches ----
static cudaStream_t s_side = 0;
static cudaEvent_t ev_fork = 0, ev_join = 0, ev_fork2 = 0, ev_join2 = 0;
struct StreamInit {
    StreamInit() {
        cudaStreamCreateWithFlags(&s_side, cudaStreamNonBlocking);
        cudaEventCreateWithFlags(&ev_fork,  cudaEventDisableTiming);
        cudaEventCreateWithFlags(&ev_join,  cudaEventDisableTiming);
        cudaEventCreateWithFlags(&ev_fork2, cudaEventDisableTiming);
        cudaEventCreateWithFlags(&ev_join2, cudaEventDisableTiming);
    }
};
static StreamInit g_stream_init;

// ---- helpers ----
__device__ __forceinline__ void split_bf16(float v, __nv_bfloat16& h, __nv_bfloat16& l) {
    h = __float2bfloat16_rn(v);
    l = __float2bfloat16_rn(v - __bfloat162float(h));
}
__device__ __forceinline__ uint32_t smem_u32(const void* p) {
    uint32_t a;
    asm("{ .reg .u64 t; cvta.to.shared.u64 t, %1; cvt.u32.u64 %0, t; }" : "=r"(a) : "l"(p));
    return a;
}
__device__ __forceinline__ void cp16(uint32_t dst, const void* src, bool pred) {
    uint32_t sz = pred ? 16u : 0u;
    asm volatile("cp.async.cg.shared.global [%0], [%1], 16, %2;"
                 :: "r"(dst), "l"(src), "r"(sz) : "memory");
}
#define CP_COMMIT() asm volatile("cp.async.commit_group;" ::: "memory")
#define CP_WAIT(n)  asm volatile("cp.async.wait_group %0;" :: "n"(n) : "memory")

__device__ __forceinline__ void mma_bf16(float* d, const uint32_t* a, const uint32_t* b) {
    asm volatile(
        "mma.sync.aligned.m16n8k16.row.col.f32.bf16.bf16.f32 "
        "{%0,%1,%2,%3}, {%4,%5,%6,%7}, {%8,%9}, {%0,%1,%2,%3};\n"
        : "+f"(d[0]), "+f"(d[1]), "+f"(d[2]), "+f"(d[3])
        : "r"(a[0]), "r"(a[1]), "r"(a[2]), "r"(a[3]), "r"(b[0]), "r"(b[1]));
}

// ===================================================================
// 1) centroids
// ===================================================================
__global__ void centroid_kernel(const float* __restrict__ coords9,
                                float* __restrict__ cent, int N) {
    int i = blockIdx.x * blockDim.x + threadIdx.x;
    if (i >= N) return;
    const float inv3 = 1.0f / 3.0f;
#pragma unroll
    for (int c = 0; c < 3; c++) {
        float s = coords9[i * 9 + c] + coords9[i * 9 + 3 + c] + coords9[i * 9 + 6 + c];
        cent[i * 3 + c] = s * inv3;
    }
}

// ===================================================================
// 2) weight convert: fp32 -> bf16 hi/lo for wq,wk,wv,wo
// ===================================================================
__global__ void convert_w_kernel(const float* __restrict__ wq, const float* __restrict__ wk,
                                 const float* __restrict__ wv, const float* __restrict__ wo) {
    int w = blockIdx.y;
    const float* src = (w == 0) ? wq : (w == 1) ? wk : (w == 2) ? wv : wo;
    __nv_bfloat16* hd = g_wh + (size_t)w * WSZ;
    __nv_bfloat16* ld = g_wl + (size_t)w * WSZ;
    int idx = (blockIdx.x * 256 + threadIdx.x) * 4;
    float4 v = *(const float4*)(src + idx);
    __nv_bfloat16 h0, h1, h2, h3, l0, l1, l2, l3;
    split_bf16(v.x, h0, l0); split_bf16(v.y, h1, l1);
    split_bf16(v.z, h2, l2); split_bf16(v.w, h3, l3);
    *(__nv_bfloat162*)(hd + idx)     = __nv_bfloat162(h0, h1);
    *(__nv_bfloat162*)(hd + idx + 2) = __nv_bfloat162(h2, h3);
    *(__nv_bfloat162*)(ld + idx)     = __nv_bfloat162(l0, l1);
    *(__nv_bfloat162*)(ld + idx + 2) = __nv_bfloat162(l2, l3);
}

// ===================================================================
// 3) pos encoder + assembly, writes pe directly as bf16 hi/lo
// ===================================================================
__global__ void posenc_kernel(const float* __restrict__ x,
                              const float* __restrict__ prompt,
                              const float* __restrict__ cent,
                              const float* __restrict__ w1,
                              const float* __restrict__ b1,
                              const float* __restrict__ lng,
                              const float* __restrict__ lnb,
                              __nv_bfloat16* __restrict__ peh,
                              __nv_bfloat16* __restrict__ pel, int N) {
    int i = blockIdx.x;
    int t = threadIdx.x;   // 0..127
    __shared__ float red[128];

    float cx = cent[i * 3 + 0], cy = cent[i * 3 + 1], cz = cent[i * 3 + 2];
    float h = cx * w1[t * 3 + 0] + cy * w1[t * 3 + 1] + cz * w1[t * 3 + 2] + b1[t];
    float gel = 0.5f * h * (1.0f + erff(h * 0.70710678118654752f));

    red[t] = gel;
    __syncthreads();
    for (int s = 64; s > 0; s >>= 1) { if (t < s) red[t] += red[t + s]; __syncthreads(); }
    float mu = red[0] * (1.0f / 128.0f);
    __syncthreads();
    float d = gel - mu;
    red[t] = d * d;
    __syncthreads();
    for (int s = 64; s > 0; s >>= 1) { if (t < s) red[t] += red[t + s]; __syncthreads(); }
    float var = red[0] * (1.0f / 128.0f);
    float y = d * rsqrtf(var + 1e-5f) * lng[t] + lnb[t];

    __nv_bfloat16 hh, ll;
    split_bf16(y, hh, ll);
    peh[(size_t)i * EDIM + 384 + t] = hh;
    pel[(size_t)i * EDIM + 384 + t] = ll;
    for (int c = t; c < 384; c += 128) {
        float v = x[(size_t)i * EDIM + c] + prompt[c];
        split_bf16(v, hh, ll);
        peh[(size_t)i * EDIM + c] = hh;
        pel[(size_t)i * EDIM + c] = ll;
    }
}

// ===================================================================
// 4) per-row k-NN top-32 via radix select on float bits (set semantics;
//    tie-break lower index in boundary bin = jax.lax.top_k).
// ===================================================================
#define TKBINS 2048
__global__ void __launch_bounds__(256)
topk_kernel(const float* __restrict__ cent, int* __restrict__ topk, int N) {
    __shared__ uint32_t keys[NMAX];
    __shared__ int      hist[TKBINS];
    __shared__ uint32_t bufk[NMAX];
    __shared__ uint16_t bufi[NMAX];
    __shared__ int      s_below, s_buf, s_binB, s_cbelow;

    int i = blockIdx.x;
    int t = threadIdx.x;

    for (int b = t; b < TKBINS; b += 256) hist[b] = 0;
    if (t == 0) { s_below = 0; s_buf = 0; }
    __syncthreads();

    float xi = cent[3 * i], yi = cent[3 * i + 1], zi = cent[3 * i + 2];
    for (int j = t; j < N; j += 256) {
        float dx = xi - cent[3 * j], dy = yi - cent[3 * j + 1], dz = zi - cent[3 * j + 2];
        float d = sqrtf(dx * dx + dy * dy + dz * dz);
        uint32_t key = __float_as_uint(d);
        keys[j] = key;
        atomicAdd(&hist[key >> 21], 1);
    }
    __syncthreads();

    if (t < 32) {
        int s = 0;
#pragma unroll
        for (int b = 0; b < 64; b++) s += hist[t * 64 + b];
        int excl = s;
#pragma unroll
        for (int off = 1; off < 32; off <<= 1) {
            int n = __shfl_up_sync(0xffffffffu, excl, off);
            if ((t & 31) >= off) excl += n;
        }
        excl -= s;
        if (excl < KNN && KNN <= excl + s) {
            int base = excl;
            for (int b = 0; b < 64; b++) {
                int h = hist[t * 64 + b];
                if (base < KNN && KNN <= base + h) {
                    s_binB = t * 64 + b;
                    s_cbelow = base;
                    break;
                }
                base += h;
            }
        }
    }
    __syncthreads();
    int binB = s_binB;
    int cbelow = s_cbelow;

    for (int j = t; j < N; j += 256) {
        uint32_t key = keys[j];
        int b = key >> 21;
        if (b < binB) {
            int slot = atomicAdd(&s_below, 1);
            topk[i * KNN + slot] = j;
        } else if (b == binB) {
            int s = atomicAdd(&s_buf, 1);
            bufk[s] = key;
            bufi[s] = (uint16_t)j;
        }
    }
    __syncthreads();

    int nb = s_buf;
    int need = KNN - cbelow;
    for (int e = t; e < nb; e += 256) {
        uint32_t ke = bufk[e];
        int ie = bufi[e];
        int rank = 0;
        for (int f = 0; f < nb; f++) {
            uint32_t kf = bufk[f];
            if (kf < ke || (kf == ke && (int)bufi[f] < ie)) rank++;
        }
        if (rank < need) topk[i * KNN + cbelow + rank] = ie;
    }
}

// ===================================================================
// 5) bf16 split GEMM with cp.async double buffering; runtime K-range.
// ===================================================================
#define KC 32
#define LSTRIDE 40
#define MATSZ (128 * LSTRIDE)
#define GSMEM (2 * 4 * MATSZ * 2)

__global__ void __launch_bounds__(256, 2)
gemm_bf16_split(const __nv_bfloat16* __restrict__ Ahi, const __nv_bfloat16* __restrict__ Alo,
                const __nv_bfloat16* __restrict__ Bh0, const __nv_bfloat16* __restrict__ Bl0,
                const __nv_bfloat16* __restrict__ Bh1, const __nv_bfloat16* __restrict__ Bl1,
                const __nv_bfloat16* __restrict__ Bh2, const __nv_bfloat16* __restrict__ Bl2,
                const float* __restrict__ bias0, const float* __restrict__ bias1,
                const float* __restrict__ bias2,
                float* __restrict__ C0, float* __restrict__ C1, float* __restrict__ C2,
                int M, int kstart, int knch, int addbias) {
    extern __shared__ __nv_bfloat16 sm[];
    uint32_t smb = smem_u32(sm);

    int tid  = threadIdx.x;
    int wid  = tid >> 5;
    int lane = tid & 31;
    int wm   = wid >> 2;
    int wn   = wid & 3;

    int sel = blockIdx.x >> 2;
    int bn  = (blockIdx.x & 3) * 128;
    int bm  = blockIdx.y * 128;

    const __nv_bfloat16* Bh = (sel == 0) ? Bh0 : (sel == 1) ? Bh1 : Bh2;
    const __nv_bfloat16* Bl = (sel == 0) ? Bl0 : (sel == 1) ? Bl1 : Bl2;
    const float* bias = (sel == 0) ? bias0 : (sel == 1) ? bias1 : bias2;
    float*       C    = (sel == 0) ? C0 : (sel == 1) ? C1 : C2;

    float acc[4][4][4];
#pragma unroll
    for (int a = 0; a < 4; a++)
#pragma unroll
        for (int b = 0; b < 4; b++)
#pragma unroll
            for (int c = 0; c < 4; c++) acc[a][b][c] = 0.0f;

    auto load_stage = [&](int s, int ch) {
        int kt = ch * KC;
        uint32_t sb = smb + (uint32_t)s * 4 * MATSZ * 2;
        for (int i = tid; i < 512; i += 256) {
            int row = i >> 2;
            int c   = (i & 3) * 8;
            uint32_t off = (uint32_t)(row * LSTRIDE + c) * 2;
            int am = bm + row;
            bool av = am < M;
            int amc = av ? am : 0;
            cp16(sb + off,             Ahi + (size_t)amc * EDIM + kt + c, av);
            cp16(sb + MATSZ * 2 + off, Alo + (size_t)amc * EDIM + kt + c, av);
            cp16(sb + MATSZ * 4 + off, Bh + (size_t)(bn + row) * EDIM + kt + c, true);
            cp16(sb + MATSZ * 6 + off, Bl + (size_t)(bn + row) * EDIM + kt + c, true);
        }
    };

    load_stage(0, kstart);
    CP_COMMIT();

    for (int cc = 0; cc < knch; cc++) {
        int s = cc & 1;
        if (cc + 1 < knch) {
            load_stage(s ^ 1, kstart + cc + 1);
            CP_COMMIT();
            CP_WAIT(1);
        } else {
            CP_WAIT(0);
        }
        __syncthreads();

        const __nv_bfloat16* base = sm + (size_t)s * 4 * MATSZ;
#pragma unroll
        for (int term = 0; term < 3; term++) {
            const __nv_bfloat16* As = base + (term == 2 ? MATSZ : 0);
            const __nv_bfloat16* Bs = base + 2 * MATSZ + (term == 1 ? MATSZ : 0);
#pragma unroll
            for (int ks = 0; ks < 2; ks++) {
                int k0 = ks * 16 + 2 * (lane & 3);
                uint32_t afr[4][4];
                uint32_t bfr[4][2];
#pragma unroll
                for (int mt = 0; mt < 4; mt++) {
                    int r = wm * 64 + mt * 16 + (lane >> 2);
                    const __nv_bfloat16* p = As + r * LSTRIDE + k0;
                    afr[mt][0] = *(const uint32_t*)p;
                    afr[mt][1] = *(const uint32_t*)(p + 8 * LSTRIDE);
                    afr[mt][2] = *(const uint32_t*)(p + 8);
                    afr[mt][3] = *(const uint32_t*)(p + 8 * LSTRIDE + 8);
                }
#pragma unroll
                for (int nt = 0; nt < 4; nt++) {
                    int n = wn * 32 + nt * 8 + (lane >> 2);
                    const __nv_bfloat16* p = Bs + n * LSTRIDE + k0;
                    bfr[nt][0] = *(const uint32_t*)p;
                    bfr[nt][1] = *(const uint32_t*)(p + 8);
                }
#pragma unroll
                for (int mt = 0; mt < 4; mt++)
#pragma unroll
                    for (int nt = 0; nt < 4; nt++)
                        mma_bf16(acc[mt][nt], afr[mt], bfr[nt]);
            }
        }
        __syncthreads();
    }

#pragma unroll
    for (int mt = 0; mt < 4; mt++) {
#pragma unroll
        for (int nt = 0; nt < 4; nt++) {
            int row0 = bm + wm * 64 + mt * 16 + (lane >> 2);
            int col  = bn + wn * 32 + nt * 8 + 2 * (lane & 3);
            float b0 = addbias ? bias[col] : 0.0f;
            float b1 = addbias ? bias[col + 1] : 0.0f;
#pragma unroll
            for (int half = 0; half < 2; half++) {
                int r = row0 + half * 8;
                if (r < M) {
                    float v0 = acc[mt][nt][half * 2 + 0] + b0;
                    float v1 = acc[mt][nt][half * 2 + 1] + b1;
                    *(float2*)(C + (size_t)r * EDIM + col) = make_float2(v0, v1);
                }
            }
        }
    }
}

// ===================================================================
// 6) sparse gather attention v3: coalesced lane=dim loads (as R13) +
//    butterfly transpose-reduction (31 shfls, depth 5) instead of 32
//    serial warp reductions. Block = 1 query, 8 head-warps.
// ===================================================================
__global__ void __launch_bounds__(256)
attn_kernel(const float* __restrict__ q,
            const float* __restrict__ k,
            const float* __restrict__ v,
            const int* __restrict__ topk,
            __nv_bfloat16* __restrict__ ctxh,
            __nv_bfloat16* __restrict__ ctxl, int N) {
    int i = blockIdx.x;
    int lane = threadIdx.x & 31;
    int h = threadIdx.x >> 5;
    __shared__ int idx_s[KNN];
    if (threadIdx.x < KNN) idx_s[threadIdx.x] = topk[i * KNN + threadIdx.x];
    __syncthreads();

    float2 q2 = *(const float2*)(q + (size_t)i * EDIM + h * DHD + 2 * lane);

    // partial dot for every neighbor (coalesced: whole warp reads one row)
    float sarr[KNN];
#pragma unroll
    for (int j = 0; j < KNN; j++) {
        int m = idx_s[j];
        float2 k2 = *(const float2*)(k + (size_t)m * EDIM + h * DHD + 2 * lane);
        sarr[j] = q2.x * k2.x + q2.y * k2.y;
    }
    // butterfly transpose-reduce: lane l ends with full dot of neighbor l.
    // Round off: pair (a, a+off); lanes with (lane&off)==0 take neighbor-bit 0.
#pragma unroll
    for (int off = 16; off; off >>= 1) {
#pragma unroll
        for (int a = 0; a < 16; a++) {
            if (a < off) {
                float lo = sarr[a], hi = sarr[a + off];
                float sent = (lane & off) ? lo : hi;
                float recv = __shfl_xor_sync(0xffffffffu, sent, off);
                sarr[a] = ((lane & off) ? hi : lo) + recv;
            }
        }
    }
    float s = sarr[0] * 0.125f;   // score for neighbor `lane`, /sqrt(64)

    // softmax across 32 lanes
    float mx = s;
#pragma unroll
    for (int off = 16; off; off >>= 1) mx = fmaxf(mx, __shfl_xor_sync(0xffffffffu, mx, off));
    float e = expf(s - mx);
    float sum = e;
#pragma unroll
    for (int off = 16; off; off >>= 1) sum += __shfl_xor_sync(0xffffffffu, sum, off);
    float p = e / sum;

    // V phase: lane = 2 dims, broadcast p_j (coalesced)
    float2 acc = make_float2(0.f, 0.f);
#pragma unroll
    for (int j = 0; j < KNN; j++) {
        float pj = __shfl_sync(0xffffffffu, p, j);
        int mj = idx_s[j];
        float2 v2 = *(const float2*)(v + (size_t)mj * EDIM + h * DHD + 2 * lane);
        acc.x += pj * v2.x;
        acc.y += pj * v2.y;
    }
    __nv_bfloat16 h0, l0, h1, l1;
    split_bf16(acc.x, h0, l0);
    split_bf16(acc.y, h1, l1);
    size_t o = (size_t)i * EDIM + h * DHD + 2 * lane;
    *(__nv_bfloat162*)(ctxh + o) = __nv_bfloat162(h0, h1);
    *(__nv_bfloat162*)(ctxl + o) = __nv_bfloat162(l0, l1);
}

// ===================================================================
// 7) combine split-K partials + bias, sanitize, clamp -> out
// ===================================================================
__global__ void combine_kernel(const float* __restrict__ p0, const float* __restrict__ p1,
                               const float* __restrict__ bias, float* __restrict__ out,
                               int total4) {
    int i = blockIdx.x * 256 + threadIdx.x;
    if (i >= total4) return;
    int idx = i * 4;
    float4 a = *(const float4*)(p0 + idx);
    float4 b = *(const float4*)(p1 + idx);
    float4 bs = *(const float4*)(bias + (idx & (EDIM - 1)));
    float v0 = a.x + b.x + bs.x;
    float v1 = a.y + b.y + bs.y;
    float v2 = a.z + b.z + bs.z;
    float v3 = a.w + b.w + bs.w;
    if (isnan(v0)) v0 = 0.0f;
    if (isnan(v1)) v1 = 0.0f;
    if (isnan(v2)) v2 = 0.0f;
    if (isnan(v3)) v3 = 0.0f;
    v0 = fminf(fmaxf(v0, -CLAMPV), CLAMPV);
    v1 = fminf(fmaxf(v1, -CLAMPV), CLAMPV);
    v2 = fminf(fmaxf(v2, -CLAMPV), CLAMPV);
    v3 = fminf(fmaxf(v3, -CLAMPV), CLAMPV);
    *(float4*)(out + idx) = make_float4(v0, v1, v2, v3);
}

// ===================================================================
extern "C" void kernel_launch(void* const* d_in, const int* in_sizes, int n_in,
                              void* d_out, int out_size) {
    const float* x       = (const float*)d_in[0];
    const float* coords9 = (const float*)d_in[1];
    const float* prompt  = (const float*)d_in[2];
    const float* pw1     = (const float*)d_in[3];
    const float* pb1     = (const float*)d_in[4];
    const float* plng    = (const float*)d_in[5];
    const float* plnb    = (const float*)d_in[6];
    const float* wq      = (const float*)d_in[7];
    const float* wk      = (const float*)d_in[8];
    const float* wv      = (const float*)d_in[9];
    const float* bq      = (const float*)d_in[10];
    const float* bk      = (const float*)d_in[11];
    const float* bv      = (const float*)d_in[12];
    const float* wo      = (const float*)d_in[13];
    const float* bo      = (const float*)d_in[14];

    int N = in_sizes[1] / 9;

    float *cent, *qp, *kp, *vp;
    __nv_bfloat16 *peh, *pel, *ch, *cl, *wh, *wl;
    int* tk;
    cudaGetSymbolAddress((void**)&cent, g_cent);
    cudaGetSymbolAddress((void**)&peh,  g_peh);
    cudaGetSymbolAddress((void**)&pel,  g_pel);
    cudaGetSymbolAddress((void**)&qp,   g_q);
    cudaGetSymbolAddress((void**)&kp,   g_k);
    cudaGetSymbolAddress((void**)&vp,   g_v);
    cudaGetSymbolAddress((void**)&ch,   g_ch);
    cudaGetSymbolAddress((void**)&cl,   g_cl);
    cudaGetSymbolAddress((void**)&wh,   g_wh);
    cudaGetSymbolAddress((void**)&wl,   g_wl);
    cudaGetSymbolAddress((void**)&tk,   g_topk);

    cudaFuncSetAttribute(gemm_bf16_split, cudaFuncAttributeMaxDynamicSharedMemorySize, GSMEM);

    // --- main stream: centroid, then fork topk to side stream ---
    centroid_kernel<<<(N + 255) / 256, 256>>>(coords9, cent, N);
    cudaEventRecord(ev_fork, 0);
    cudaStreamWaitEvent(s_side, ev_fork, 0);
    topk_kernel<<<N, 256, 0, s_side>>>(cent, tk, N);
    cudaEventRecord(ev_join, s_side);

    // --- main stream GEMM branch ---
    convert_w_kernel<<<dim3(256, 4), 256>>>(wq, wk, wv, wo);
    posenc_kernel<<<N, 128>>>(x, prompt, cent, pw1, pb1, plng, plnb, peh, pel, N);

    int mt = (N + 127) / 128;
    gemm_bf16_split<<<dim3(12, mt), 256, GSMEM>>>(
        peh, pel,
        wh + 0 * WSZ, wl + 0 * WSZ, wh + 1 * WSZ, wl + 1 * WSZ, wh + 2 * WSZ, wl + 2 * WSZ,
        bq, bk, bv, qp, kp, vp, N, 0, 16, 1);

    // --- join topk, run attention ---
    cudaStreamWaitEvent(0, ev_join, 0);
    attn_kernel<<<N, 256>>>(qp, kp, vp, tk, ch, cl, N);

    // --- WO split-K across the two streams; q/k buffers reused as partials ---
    cudaEventRecord(ev_fork2, 0);
    cudaStreamWaitEvent(s_side, ev_fork2, 0);
    gemm_bf16_split<<<dim3(4, mt), 256, GSMEM, s_side>>>(
        ch, cl,
        wh + 3 * WSZ, wl + 3 * WSZ, wh + 3 * WSZ, wl + 3 * WSZ, wh + 3 * WSZ, wl + 3 * WSZ,
        bo, bo, bo, kp, kp, kp, N, 8, 8, 0);
    cudaEventRecord(ev_join2, s_side);
    gemm_bf16_split<<<dim3(4, mt), 256, GSMEM>>>(
        ch, cl,
        wh + 3 * WSZ, wl + 3 * WSZ, wh + 3 * WSZ, wl + 3 * WSZ, wh + 3 * WSZ, wl + 3 * WSZ,
        bo, bo, bo, qp, qp, qp, N, 0, 8, 0);
    cudaStreamWaitEvent(0, ev_join2, 0);

    int total4 = N * EDIM / 4;
    combine_kernel<<<(total4 + 255) / 256, 256>>>(qp, kp, bo, (float*)d_out, total4);
}

// round 17
// speedup vs baseline: 1.9190x; 1.0065x over previous
#include <cuda_runtime.h>
#include <cuda_bf16.h>
#include <cstdint>
#include <math.h>

#define EDIM 512
#define HEADS 8
#define DHD 64
#define KNN 32
#define NMAX 2048
#define CLAMPV 10000.0f
#define WSZ (EDIM * EDIM)

// ---- scratch (no allocations allowed) ----
__device__ float g_cent[NMAX * 3];
__device__ __nv_bfloat16 g_peh[NMAX * EDIM];
__device__ __nv_bfloat16 g_pel[NMAX * EDIM];
__device__ float g_q[NMAX * EDIM];    // QKV q; later WO partial 0
__device__ float g_k[NMAX * EDIM];    // QKV k; later WO partial 1
__device__ float g_v[NMAX * EDIM];
__device__ float g_p[NMAX * HEADS * KNN];   // softmax weights
__device__ __nv_bfloat16 g_ch[NMAX * EDIM];
__device__ __nv_bfloat16 g_cl[NMAX * EDIM];
__device__ __nv_bfloat16 g_wh[4 * WSZ];   // q,k,v,o hi
__device__ __nv_bfloat16 g_wl[4 * WSZ];   // q,k,v,o lo
__device__ int   g_topk[NMAX * KNN];

// ---- streams/events for parallel graph branches ----
static cudaStream_t s_side = 0;
static cudaEvent_t ev_fork = 0, ev_conv = 0, ev_topk = 0, ev_pos = 0,
                   ev_v = 0, ev_av = 0, ev_join2 = 0;
struct StreamInit {
    StreamInit() {
        cudaStreamCreateWithFlags(&s_side, cudaStreamNonBlocking);
        cudaEventCreateWithFlags(&ev_fork,  cudaEventDisableTiming);
        cudaEventCreateWithFlags(&ev_conv,  cudaEventDisableTiming);
        cudaEventCreateWithFlags(&ev_topk,  cudaEventDisableTiming);
        cudaEventCreateWithFlags(&ev_pos,   cudaEventDisableTiming);
        cudaEventCreateWithFlags(&ev_v,     cudaEventDisableTiming);
        cudaEventCreateWithFlags(&ev_av,    cudaEventDisableTiming);
        cudaEventCreateWithFlags(&ev_join2, cudaEventDisableTiming);
    }
};
static StreamInit g_stream_init;

// ---- helpers ----
__device__ __forceinline__ void split_bf16(float v, __nv_bfloat16& h, __nv_bfloat16& l) {
    h = __float2bfloat16_rn(v);
    l = __float2bfloat16_rn(v - __bfloat162float(h));
}
__device__ __forceinline__ uint32_t smem_u32(const void* p) {
    uint32_t a;
    asm("{ .reg .u64 t; cvta.to.shared.u64 t, %1; cvt.u32.u64 %0, t; }" : "=r"(a) : "l"(p));
    return a;
}
__device__ __forceinline__ void cp16(uint32_t dst, const void* src, bool pred) {
    uint32_t sz = pred ? 16u : 0u;
    asm volatile("cp.async.cg.shared.global [%0], [%1], 16, %2;"
                 :: "r"(dst), "l"(src), "r"(sz) : "memory");
}
#define CP_COMMIT() asm volatile("cp.async.commit_group;" ::: "memory")
#define CP_WAIT(n)  asm volatile("cp.async.wait_group %0;" :: "n"(n) : "memory")

__device__ __forceinline__ void mma_bf16(float* d, const uint32_t* a, const uint32_t* b) {
    asm volatile(
        "mma.sync.aligned.m16n8k16.row.col.f32.bf16.bf16.f32 "
        "{%0,%1,%2,%3}, {%4,%5,%6,%7}, {%8,%9}, {%0,%1,%2,%3};\n"
        : "+f"(d[0]), "+f"(d[1]), "+f"(d[2]), "+f"(d[3])
        : "r"(a[0]), "r"(a[1]), "r"(a[2]), "r"(a[3]), "r"(b[0]), "r"(b[1]));
}

// ===================================================================
// 1) centroids
// ===================================================================
__global__ void centroid_kernel(const float* __restrict__ coords9,
                                float* __restrict__ cent, int N) {
    int i = blockIdx.x * blockDim.x + threadIdx.x;
    if (i >= N) return;
    const float inv3 = 1.0f / 3.0f;
#pragma unroll
    for (int c = 0; c < 3; c++) {
        float s = coords9[i * 9 + c] + coords9[i * 9 + 3 + c] + coords9[i * 9 + 6 + c];
        cent[i * 3 + c] = s * inv3;
    }
}

// ===================================================================
// 2) weight convert: fp32 -> bf16 hi/lo for wq,wk,wv,wo
// ===================================================================
__global__ void convert_w_kernel(const float* __restrict__ wq, const float* __restrict__ wk,
                                 const float* __restrict__ wv, const float* __restrict__ wo) {
    int w = blockIdx.y;
    const float* src = (w == 0) ? wq : (w == 1) ? wk : (w == 2) ? wv : wo;
    __nv_bfloat16* hd = g_wh + (size_t)w * WSZ;
    __nv_bfloat16* ld = g_wl + (size_t)w * WSZ;
    int idx = (blockIdx.x * 256 + threadIdx.x) * 4;
    float4 v = *(const float4*)(src + idx);
    __nv_bfloat16 h0, h1, h2, h3, l0, l1, l2, l3;
    split_bf16(v.x, h0, l0); split_bf16(v.y, h1, l1);
    split_bf16(v.z, h2, l2); split_bf16(v.w, h3, l3);
    *(__nv_bfloat162*)(hd + idx)     = __nv_bfloat162(h0, h1);
    *(__nv_bfloat162*)(hd + idx + 2) = __nv_bfloat162(h2, h3);
    *(__nv_bfloat162*)(ld + idx)     = __nv_bfloat162(l0, l1);
    *(__nv_bfloat162*)(ld + idx + 2) = __nv_bfloat162(l2, l3);
}

// ===================================================================
// 3) pos encoder + assembly, writes pe directly as bf16 hi/lo
// ===================================================================
__global__ void posenc_kernel(const float* __restrict__ x,
                              const float* __restrict__ prompt,
                              const float* __restrict__ cent,
                              const float* __restrict__ w1,
                              const float* __restrict__ b1,
                              const float* __restrict__ lng,
                              const float* __restrict__ lnb,
                              __nv_bfloat16* __restrict__ peh,
                              __nv_bfloat16* __restrict__ pel, int N) {
    int i = blockIdx.x;
    int t = threadIdx.x;   // 0..127
    __shared__ float red[128];

    float cx = cent[i * 3 + 0], cy = cent[i * 3 + 1], cz = cent[i * 3 + 2];
    float h = cx * w1[t * 3 + 0] + cy * w1[t * 3 + 1] + cz * w1[t * 3 + 2] + b1[t];
    float gel = 0.5f * h * (1.0f + erff(h * 0.70710678118654752f));

    red[t] = gel;
    __syncthreads();
    for (int s = 64; s > 0; s >>= 1) { if (t < s) red[t] += red[t + s]; __syncthreads(); }
    float mu = red[0] * (1.0f / 128.0f);
    __syncthreads();
    float d = gel - mu;
    red[t] = d * d;
    __syncthreads();
    for (int s = 64; s > 0; s >>= 1) { if (t < s) red[t] += red[t + s]; __syncthreads(); }
    float var = red[0] * (1.0f / 128.0f);
    float y = d * rsqrtf(var + 1e-5f) * lng[t] + lnb[t];

    __nv_bfloat16 hh, ll;
    split_bf16(y, hh, ll);
    peh[(size_t)i * EDIM + 384 + t] = hh;
    pel[(size_t)i * EDIM + 384 + t] = ll;
    for (int c = t; c < 384; c += 128) {
        float v = x[(size_t)i * EDIM + c] + prompt[c];
        split_bf16(v, hh, ll);
        peh[(size_t)i * EDIM + c] = hh;
        pel[(size_t)i * EDIM + c] = ll;
    }
}

// ===================================================================
// 4) per-row k-NN top-32 via radix select on float bits
// ===================================================================
#define TKBINS 2048
__global__ void __launch_bounds__(256)
topk_kernel(const float* __restrict__ cent, int* __restrict__ topk, int N) {
    __shared__ uint32_t keys[NMAX];
    __shared__ int      hist[TKBINS];
    __shared__ uint32_t bufk[NMAX];
    __shared__ uint16_t bufi[NMAX];
    __shared__ int      s_below, s_buf, s_binB, s_cbelow;

    int i = blockIdx.x;
    int t = threadIdx.x;

    for (int b = t; b < TKBINS; b += 256) hist[b] = 0;
    if (t == 0) { s_below = 0; s_buf = 0; }
    __syncthreads();

    float xi = cent[3 * i], yi = cent[3 * i + 1], zi = cent[3 * i + 2];
    for (int j = t; j < N; j += 256) {
        float dx = xi - cent[3 * j], dy = yi - cent[3 * j + 1], dz = zi - cent[3 * j + 2];
        float d = sqrtf(dx * dx + dy * dy + dz * dz);
        uint32_t key = __float_as_uint(d);
        keys[j] = key;
        atomicAdd(&hist[key >> 21], 1);
    }
    __syncthreads();

    if (t < 32) {
        int s = 0;
#pragma unroll
        for (int b = 0; b < 64; b++) s += hist[t * 64 + b];
        int excl = s;
#pragma unroll
        for (int off = 1; off < 32; off <<= 1) {
            int n = __shfl_up_sync(0xffffffffu, excl, off);
            if ((t & 31) >= off) excl += n;
        }
        excl -= s;
        if (excl < KNN && KNN <= excl + s) {
            int base = excl;
            for (int b = 0; b < 64; b++) {
                int h = hist[t * 64 + b];
                if (base < KNN && KNN <= base + h) {
                    s_binB = t * 64 + b;
                    s_cbelow = base;
                    break;
                }
                base += h;
            }
        }
    }
    __syncthreads();
    int binB = s_binB;
    int cbelow = s_cbelow;

    for (int j = t; j < N; j += 256) {
        uint32_t key = keys[j];
        int b = key >> 21;
        if (b < binB) {
            int slot = atomicAdd(&s_below, 1);
            topk[i * KNN + slot] = j;
        } else if (b == binB) {
            int s = atomicAdd(&s_buf, 1);
            bufk[s] = key;
            bufi[s] = (uint16_t)j;
        }
    }
    __syncthreads();

    int nb = s_buf;
    int need = KNN - cbelow;
    for (int e = t; e < nb; e += 256) {
        uint32_t ke = bufk[e];
        int ie = bufi[e];
        int rank = 0;
        for (int f = 0; f < nb; f++) {
            uint32_t kf = bufk[f];
            if (kf < ke || (kf == ke && (int)bufi[f] < ie)) rank++;
        }
        if (rank < need) topk[i * KNN + cbelow + rank] = ie;
    }
}

// ===================================================================
// 5) bf16 split GEMM with cp.async double buffering; runtime K-range.
// ===================================================================
#define KC 32
#define LSTRIDE 40
#define MATSZ (128 * LSTRIDE)
#define GSMEM (2 * 4 * MATSZ * 2)

__global__ void __launch_bounds__(256, 2)
gemm_bf16_split(const __nv_bfloat16* __restrict__ Ahi, const __nv_bfloat16* __restrict__ Alo,
                const __nv_bfloat16* __restrict__ Bh0, const __nv_bfloat16* __restrict__ Bl0,
                const __nv_bfloat16* __restrict__ Bh1, const __nv_bfloat16* __restrict__ Bl1,
                const __nv_bfloat16* __restrict__ Bh2, const __nv_bfloat16* __restrict__ Bl2,
                const float* __restrict__ bias0, const float* __restrict__ bias1,
                const float* __restrict__ bias2,
                float* __restrict__ C0, float* __restrict__ C1, float* __restrict__ C2,
                int M, int kstart, int knch, int addbias) {
    extern __shared__ __nv_bfloat16 sm[];
    uint32_t smb = smem_u32(sm);

    int tid  = threadIdx.x;
    int wid  = tid >> 5;
    int lane = tid & 31;
    int wm   = wid >> 2;
    int wn   = wid & 3;

    int sel = blockIdx.x >> 2;
    int bn  = (blockIdx.x & 3) * 128;
    int bm  = blockIdx.y * 128;

    const __nv_bfloat16* Bh = (sel == 0) ? Bh0 : (sel == 1) ? Bh1 : Bh2;
    const __nv_bfloat16* Bl = (sel == 0) ? Bl0 : (sel == 1) ? Bl1 : Bl2;
    const float* bias = (sel == 0) ? bias0 : (sel == 1) ? bias1 : bias2;
    float*       C    = (sel == 0) ? C0 : (sel == 1) ? C1 : C2;

    float acc[4][4][4];
#pragma unroll
    for (int a = 0; a < 4; a++)
#pragma unroll
        for (int b = 0; b < 4; b++)
#pragma unroll
            for (int c = 0; c < 4; c++) acc[a][b][c] = 0.0f;

    auto load_stage = [&](int s, int ch) {
        int kt = ch * KC;
        uint32_t sb = smb + (uint32_t)s * 4 * MATSZ * 2;
        for (int i = tid; i < 512; i += 256) {
            int row = i >> 2;
            int c   = (i & 3) * 8;
            uint32_t off = (uint32_t)(row * LSTRIDE + c) * 2;
            int am = bm + row;
            bool av = am < M;
            int amc = av ? am : 0;
            cp16(sb + off,             Ahi + (size_t)amc * EDIM + kt + c, av);
            cp16(sb + MATSZ * 2 + off, Alo + (size_t)amc * EDIM + kt + c, av);
            cp16(sb + MATSZ * 4 + off, Bh + (size_t)(bn + row) * EDIM + kt + c, true);
            cp16(sb + MATSZ * 6 + off, Bl + (size_t)(bn + row) * EDIM + kt + c, true);
        }
    };

    load_stage(0, kstart);
    CP_COMMIT();

    for (int cc = 0; cc < knch; cc++) {
        int s = cc & 1;
        if (cc + 1 < knch) {
            load_stage(s ^ 1, kstart + cc + 1);
            CP_COMMIT();
            CP_WAIT(1);
        } else {
            CP_WAIT(0);
        }
        __syncthreads();

        const __nv_bfloat16* base = sm + (size_t)s * 4 * MATSZ;
#pragma unroll
        for (int term = 0; term < 3; term++) {
            const __nv_bfloat16* As = base + (term == 2 ? MATSZ : 0);
            const __nv_bfloat16* Bs = base + 2 * MATSZ + (term == 1 ? MATSZ : 0);
#pragma unroll
            for (int ks = 0; ks < 2; ks++) {
                int k0 = ks * 16 + 2 * (lane & 3);
                uint32_t afr[4][4];
                uint32_t bfr[4][2];
#pragma unroll
                for (int mt = 0; mt < 4; mt++) {
                    int r = wm * 64 + mt * 16 + (lane >> 2);
                    const __nv_bfloat16* p = As + r * LSTRIDE + k0;
                    afr[mt][0] = *(const uint32_t*)p;
                    afr[mt][1] = *(const uint32_t*)(p + 8 * LSTRIDE);
                    afr[mt][2] = *(const uint32_t*)(p + 8);
                    afr[mt][3] = *(const uint32_t*)(p + 8 * LSTRIDE + 8);
                }
#pragma unroll
                for (int nt = 0; nt < 4; nt++) {
                    int n = wn * 32 + nt * 8 + (lane >> 2);
                    const __nv_bfloat16* p = Bs + n * LSTRIDE + k0;
                    bfr[nt][0] = *(const uint32_t*)p;
                    bfr[nt][1] = *(const uint32_t*)(p + 8);
                }
#pragma unroll
                for (int mt = 0; mt < 4; mt++)
#pragma unroll
                    for (int nt = 0; nt < 4; nt++)
                        mma_bf16(acc[mt][nt], afr[mt], bfr[nt]);
            }
        }
        __syncthreads();
    }

#pragma unroll
    for (int mt = 0; mt < 4; mt++) {
#pragma unroll
        for (int nt = 0; nt < 4; nt++) {
            int row0 = bm + wm * 64 + mt * 16 + (lane >> 2);
            int col  = bn + wn * 32 + nt * 8 + 2 * (lane & 3);
            float b0 = addbias ? bias[col] : 0.0f;
            float b1 = addbias ? bias[col + 1] : 0.0f;
#pragma unroll
            for (int half = 0; half < 2; half++) {
                int r = row0 + half * 8;
                if (r < M) {
                    float v0 = acc[mt][nt][half * 2 + 0] + b0;
                    float v1 = acc[mt][nt][half * 2 + 1] + b1;
                    *(float2*)(C + (size_t)r * EDIM + col) = make_float2(v0, v1);
                }
            }
        }
    }
}

// ===================================================================
// 6a) attention scores: coalesced partials + butterfly transpose,
//     softmax -> p in global. Block = 1 query, 8 head-warps.
// ===================================================================
__global__ void __launch_bounds__(256)
attn_score_kernel(const float* __restrict__ q,
                  const float* __restrict__ k,
                  const int* __restrict__ topk,
                  float* __restrict__ p_out, int N) {
    int i = blockIdx.x;
    int lane = threadIdx.x & 31;
    int h = threadIdx.x >> 5;
    __shared__ int idx_s[KNN];
    if (threadIdx.x < KNN) idx_s[threadIdx.x] = topk[i * KNN + threadIdx.x];
    __syncthreads();

    float2 q2 = *(const float2*)(q + (size_t)i * EDIM + h * DHD + 2 * lane);

    float sarr[KNN];
#pragma unroll
    for (int j = 0; j < KNN; j++) {
        int m = idx_s[j];
        float2 k2 = *(const float2*)(k + (size_t)m * EDIM + h * DHD + 2 * lane);
        sarr[j] = q2.x * k2.x + q2.y * k2.y;
    }
#pragma unroll
    for (int off = 16; off; off >>= 1) {
#pragma unroll
        for (int a = 0; a < 16; a++) {
            if (a < off) {
                float lo = sarr[a], hi = sarr[a + off];
                float sent = (lane & off) ? lo : hi;
                float recv = __shfl_xor_sync(0xffffffffu, sent, off);
                sarr[a] = ((lane & off) ? hi : lo) + recv;
            }
        }
    }
    float s = sarr[0] * 0.125f;

    float mx = s;
#pragma unroll
    for (int off = 16; off; off >>= 1) mx = fmaxf(mx, __shfl_xor_sync(0xffffffffu, mx, off));
    float e = expf(s - mx);
    float sum = e;
#pragma unroll
    for (int off = 16; off; off >>= 1) sum += __shfl_xor_sync(0xffffffffu, sum, off);
    p_out[i * (HEADS * KNN) + h * KNN + lane] = e / sum;
}

// ===================================================================
// 6b) weighted-V accumulation, writes ctx as bf16 hi/lo
// ===================================================================
__global__ void __launch_bounds__(256)
attn_v_kernel(const float* __restrict__ v,
              const float* __restrict__ p_in,
              const int* __restrict__ topk,
              __nv_bfloat16* __restrict__ ctxh,
              __nv_bfloat16* __restrict__ ctxl, int N) {
    int i = blockIdx.x;
    int lane = threadIdx.x & 31;
    int h = threadIdx.x >> 5;
    __shared__ int idx_s[KNN];
    if (threadIdx.x < KNN) idx_s[threadIdx.x] = topk[i * KNN + threadIdx.x];
    __syncthreads();

    float p = p_in[i * (HEADS * KNN) + h * KNN + lane];

    float2 acc = make_float2(0.f, 0.f);
#pragma unroll
    for (int j = 0; j < KNN; j++) {
        float pj = __shfl_sync(0xffffffffu, p, j);
        int mj = idx_s[j];
        float2 v2 = *(const float2*)(v + (size_t)mj * EDIM + h * DHD + 2 * lane);
        acc.x += pj * v2.x;
        acc.y += pj * v2.y;
    }
    __nv_bfloat16 h0, l0, h1, l1;
    split_bf16(acc.x, h0, l0);
    split_bf16(acc.y, h1, l1);
    size_t o = (size_t)i * EDIM + h * DHD + 2 * lane;
    *(__nv_bfloat162*)(ctxh + o) = __nv_bfloat162(h0, h1);
    *(__nv_bfloat162*)(ctxl + o) = __nv_bfloat162(l0, l1);
}

// ===================================================================
// 7) combine split-K partials + bias, sanitize, clamp -> out
// ===================================================================
__global__ void combine_kernel(const float* __restrict__ p0, const float* __restrict__ p1,
                               const float* __restrict__ bias, float* __restrict__ out,
                               int total4) {
    int i = blockIdx.x * 256 + threadIdx.x;
    if (i >= total4) return;
    int idx = i * 4;
    float4 a = *(const float4*)(p0 + idx);
    float4 b = *(const float4*)(p1 + idx);
    float4 bs = *(const float4*)(bias + (idx & (EDIM - 1)));
    float v0 = a.x + b.x + bs.x;
    float v1 = a.y + b.y + bs.y;
    float v2 = a.z + b.z + bs.z;
    float v3 = a.w + b.w + bs.w;
    if (isnan(v0)) v0 = 0.0f;
    if (isnan(v1)) v1 = 0.0f;
    if (isnan(v2)) v2 = 0.0f;
    if (isnan(v3)) v3 = 0.0f;
    v0 = fminf(fmaxf(v0, -CLAMPV), CLAMPV);
    v1 = fminf(fmaxf(v1, -CLAMPV), CLAMPV);
    v2 = fminf(fmaxf(v2, -CLAMPV), CLAMPV);
    v3 = fminf(fmaxf(v3, -CLAMPV), CLAMPV);
    *(float4*)(out + idx) = make_float4(v0, v1, v2, v3);
}

// ===================================================================
extern "C" void kernel_launch(void* const* d_in, const int* in_sizes, int n_in,
                              void* d_out, int out_size) {
    const float* x       = (const float*)d_in[0];
    const float* coords9 = (const float*)d_in[1];
    const float* prompt  = (const float*)d_in[2];
    const float* pw1     = (const float*)d_in[3];
    const float* pb1     = (const float*)d_in[4];
    const float* plng    = (const float*)d_in[5];
    const float* plnb    = (const float*)d_in[6];
    const float* wq      = (const float*)d_in[7];
    const float* wk      = (const float*)d_in[8];
    const float* wv      = (const float*)d_in[9];
    const float* bq      = (const float*)d_in[10];
    const float* bk      = (const float*)d_in[11];
    const float* bv      = (const float*)d_in[12];
    const float* wo      = (const float*)d_in[13];
    const float* bo      = (const float*)d_in[14];

    int N = in_sizes[1] / 9;

    float *cent, *qp, *kp, *vp, *pp;
    __nv_bfloat16 *peh, *pel, *ch, *cl, *wh, *wl;
    int* tk;
    cudaGetSymbolAddress((void**)&cent, g_cent);
    cudaGetSymbolAddress((void**)&peh,  g_peh);
    cudaGetSymbolAddress((void**)&pel,  g_pel);
    cudaGetSymbolAddress((void**)&qp,   g_q);
    cudaGetSymbolAddress((void**)&kp,   g_k);
    cudaGetSymbolAddress((void**)&vp,   g_v);
    cudaGetSymbolAddress((void**)&pp,   g_p);
    cudaGetSymbolAddress((void**)&ch,   g_ch);
    cudaGetSymbolAddress((void**)&cl,   g_cl);
    cudaGetSymbolAddress((void**)&wh,   g_wh);
    cudaGetSymbolAddress((void**)&wl,   g_wl);
    cudaGetSymbolAddress((void**)&tk,   g_topk);

    cudaFuncSetAttribute(gemm_bf16_split, cudaFuncAttributeMaxDynamicSharedMemorySize, GSMEM);

    int mt = (N + 127) / 128;

    // --- fork side stream: convert_w then topk (topk needs centroid) ---
    // centroid first on main so topk's input is ready.
    centroid_kernel<<<(N + 255) / 256, 256>>>(coords9, cent, N);
    cudaEventRecord(ev_fork, 0);
    cudaStreamWaitEvent(s_side, ev_fork, 0);
    convert_w_kernel<<<dim3(256, 4), 256, 0, s_side>>>(wq, wk, wv, wo);
    cudaEventRecord(ev_conv, s_side);
    topk_kernel<<<N, 256, 0, s_side>>>(cent, tk, N);
    cudaEventRecord(ev_topk, s_side);

    // --- main: posenc, then QK GEMM (needs convert) ---
    posenc_kernel<<<N, 128>>>(x, prompt, cent, pw1, pb1, plng, plnb, peh, pel, N);
    cudaEventRecord(ev_pos, 0);
    cudaStreamWaitEvent(0, ev_conv, 0);
    gemm_bf16_split<<<dim3(8, mt), 256, GSMEM>>>(
        peh, pel,
        wh + 0 * WSZ, wl + 0 * WSZ, wh + 1 * WSZ, wl + 1 * WSZ, wh + 1 * WSZ, wl + 1 * WSZ,
        bq, bk, bk, qp, kp, kp, N, 0, 16, 1);

    // --- side: V GEMM after topk + posenc ---
    cudaStreamWaitEvent(s_side, ev_pos, 0);
    gemm_bf16_split<<<dim3(4, mt), 256, GSMEM, s_side>>>(
        peh, pel,
        wh + 2 * WSZ, wl + 2 * WSZ, wh + 2 * WSZ, wl + 2 * WSZ, wh + 2 * WSZ, wl + 2 * WSZ,
        bv, bv, bv, vp, vp, vp, N, 0, 16, 1);
    cudaEventRecord(ev_v, s_side);

    // --- main: attention scores (overlaps V GEMM), then weighted V ---
    cudaStreamWaitEvent(0, ev_topk, 0);
    attn_score_kernel<<<N, 256>>>(qp, kp, tk, pp, N);
    cudaStreamWaitEvent(0, ev_v, 0);
    attn_v_kernel<<<N, 256>>>(vp, pp, tk, ch, cl, N);
    cudaEventRecord(ev_av, 0);

    // --- WO split-K across the two streams ---
    cudaStreamWaitEvent(s_side, ev_av, 0);
    gemm_bf16_split<<<dim3(4, mt), 256, GSMEM, s_side>>>(
        ch, cl,
        wh + 3 * WSZ, wl + 3 * WSZ, wh + 3 * WSZ, wl + 3 * WSZ, wh + 3 * WSZ, wl + 3 * WSZ,
        bo, bo, bo, kp, kp, kp, N, 8, 8, 0);
    cudaEventRecord(ev_join2, s_side);
    gemm_bf16_split<<<dim3(4, mt), 256, GSMEM>>>(
        ch, cl,
        wh + 3 * WSZ, wl + 3 * WSZ, wh + 3 * WSZ, wl + 3 * WSZ, wh + 3 * WSZ, wl + 3 * WSZ,
        bo, bo, bo, qp, qp, qp, N, 0, 8, 0);
    cudaStreamWaitEvent(0, ev_join2, 0);

    int total4 = N * EDIM / 4;
    combine_kernel<<<(total4 + 255) / 256, 256>>>(qp, kp, bo, (float*)d_out, total4);
}